// round 3
// baseline (speedup 1.0000x reference)
#include <cuda_runtime.h>
#include <cuda_bf16.h>
#include <math.h>

// Problem constants (fixed by the dataset)
#define Bsz 8
#define Nn  1024
#define Ff  128
#define Ee  4
#define NSTEPS 5

#define MROWS (Bsz * Nn)       // 8192
#define EF    (Ee * Ff)        // 512
#define G3F   (3 * Ff)         // 384

// ---------------- scratch (device globals: no allocations allowed) ----------
__device__ float g_buf [(size_t)Bsz * Ee * Nn * Nn];   // [b][e][n][m] scaled graph, 128MB
__device__ float a_buf [(size_t)MROWS * EF];           // a as (8192, 512): col = e*128+g
__device__ float x_buf [(size_t)MROWS * EF];           // flows as (8192, 512): col = e*128+f
__device__ float gi_buf[(size_t)MROWS * G3F];          // (8192, 384)
__device__ float gh_buf[(size_t)MROWS * G3F];          // (8192, 384)
__device__ float h_buf [(size_t)MROWS * Ff];           // current feats (8192, 128)

// ---------------- graph conversion:  g = float(graphs) * sigmoid(tw[e]) -----
// NOTE: graphs is int32 (JAX x64 disabled downcasts jnp.int64 -> int32).
__global__ void __launch_bounds__(256) convert_g_kernel(
    const int* __restrict__ graphs,
    const float* __restrict__ tw,
    float* __restrict__ g)
{
    size_t idx4 = ((size_t)blockIdx.x * blockDim.x + threadIdx.x) * 4;
    int e = (int)((idx4 >> 20) & 3);         // n*m = 2^20 per (b,e) slab; 4-elem vec never crosses
    float w = 1.0f / (1.0f + expf(-tw[e]));
    int4 gv = *(const int4*)&graphs[idx4];
    float4 ov;
    ov.x = (float)gv.x * w;
    ov.y = (float)gv.y * w;
    ov.z = (float)gv.z * w;
    ov.w = (float)gv.w * w;
    *(float4*)&g[idx4] = ov;
}

__global__ void __launch_bounds__(256) copy_h_kernel(
    const float* __restrict__ src, float* __restrict__ dst)
{
    size_t idx = (size_t)blockIdx.x * blockDim.x + threadIdx.x;
    dst[idx] = src[idx];
}

// ---------------- generic NT SGEMM:  C = A(MxK) * B(NxK)^T + bias ------------
// 128x128x16 tile, 256 threads, 8x8 microtile. All dims multiples of tile.
// grid.x = M/128, grid.y = N/128. B row-major with ldb == K. bias indexed by col.
__global__ void __launch_bounds__(256) sgemm_nt_kernel(
    const float* __restrict__ A, int lda,
    const float* __restrict__ B,          // (N x K) row-major
    const float* __restrict__ bias,       // (N,)
    float* __restrict__ C, int ldc,
    int K)
{
    __shared__ float As[16][128];
    __shared__ float Bs[16][128];

    const int bm = blockIdx.x * 128;
    const int bn = blockIdx.y * 128;
    const int tid = threadIdx.x;

    const int l_row = tid >> 2;          // 0..63
    const int l_col = (tid & 3) * 4;     // 0,4,8,12
    const int ty = tid >> 4;             // 0..15
    const int tx = tid & 15;             // 0..15

    float acc[8][8];
    #pragma unroll
    for (int i = 0; i < 8; i++)
        #pragma unroll
        for (int j = 0; j < 8; j++) acc[i][j] = 0.0f;

    for (int k0 = 0; k0 < K; k0 += 16) {
        #pragma unroll
        for (int it = 0; it < 2; it++) {
            int r = l_row + it * 64;
            float4 v = *(const float4*)&A[(size_t)(bm + r) * lda + k0 + l_col];
            As[l_col + 0][r] = v.x; As[l_col + 1][r] = v.y;
            As[l_col + 2][r] = v.z; As[l_col + 3][r] = v.w;
        }
        #pragma unroll
        for (int it = 0; it < 2; it++) {
            int r = l_row + it * 64;     // n within tile
            float4 v = *(const float4*)&B[(size_t)(bn + r) * K + k0 + l_col];
            Bs[l_col + 0][r] = v.x; Bs[l_col + 1][r] = v.y;
            Bs[l_col + 2][r] = v.z; Bs[l_col + 3][r] = v.w;
        }
        __syncthreads();

        #pragma unroll
        for (int k = 0; k < 16; k++) {
            float ar[8], br[8];
            #pragma unroll
            for (int i = 0; i < 8; i++) ar[i] = As[k][ty * 8 + i];
            #pragma unroll
            for (int j = 0; j < 8; j++) br[j] = Bs[k][tx * 8 + j];
            #pragma unroll
            for (int i = 0; i < 8; i++)
                #pragma unroll
                for (int j = 0; j < 8; j++) acc[i][j] += ar[i] * br[j];
        }
        __syncthreads();
    }

    #pragma unroll
    for (int i = 0; i < 8; i++) {
        size_t r = (size_t)(bm + ty * 8 + i);
        #pragma unroll
        for (int j = 0; j < 8; j += 4) {
            int c = tx * 8 + j;
            float4 v;
            v.x = acc[i][j + 0] + bias[bn + c + 0];
            v.y = acc[i][j + 1] + bias[bn + c + 1];
            v.z = acc[i][j + 2] + bias[bn + c + 2];
            v.w = acc[i][j + 3] + bias[bn + c + 3];
            *(float4*)&C[r * ldc + bn + c] = v;
        }
    }
}

// ---------------- flows GEMM (NN, batched over z = b*4+e) --------------------
// C[b][n][e][f] = sum_m g[b][e][n][m] * a2d[(b*1024+m)][e*128+f]
// per z: M=1024 (grid.x=8), N=128 (one tile), K=1024
__global__ void __launch_bounds__(256) sgemm_flows_kernel(
    const float* __restrict__ Gm,
    const float* __restrict__ A2d,
    float* __restrict__ Xm)
{
    const int z = blockIdx.z;
    const int b = z >> 2, e = z & 3;
    const float* A = Gm  + ((size_t)z << 20);                              // (1024x1024) lda=1024
    const float* B = A2d + (size_t)b * Nn * EF + (size_t)e * Ff;           // (1024x128)  ldb=512
    float*       C = Xm  + (size_t)b * Nn * EF + (size_t)e * Ff;           // ldc=512

    __shared__ float As[16][128];
    __shared__ float Bs[16][128];

    const int bm  = blockIdx.x * 128;
    const int tid = threadIdx.x;
    const int l_row = tid >> 2;
    const int l_col = (tid & 3) * 4;
    const int b_row = tid >> 5;          // 0..7
    const int b_col = (tid & 31) * 4;    // 0..124
    const int ty = tid >> 4, tx = tid & 15;

    float acc[8][8];
    #pragma unroll
    for (int i = 0; i < 8; i++)
        #pragma unroll
        for (int j = 0; j < 8; j++) acc[i][j] = 0.0f;

    for (int k0 = 0; k0 < 1024; k0 += 16) {
        #pragma unroll
        for (int it = 0; it < 2; it++) {
            int r = l_row + it * 64;
            float4 v = *(const float4*)&A[(size_t)(bm + r) * 1024 + k0 + l_col];
            As[l_col + 0][r] = v.x; As[l_col + 1][r] = v.y;
            As[l_col + 2][r] = v.z; As[l_col + 3][r] = v.w;
        }
        #pragma unroll
        for (int it = 0; it < 2; it++) {
            int r = b_row + it * 8;      // k within tile
            *(float4*)&Bs[r][b_col] = *(const float4*)&B[(size_t)(k0 + r) * EF + b_col];
        }
        __syncthreads();

        #pragma unroll
        for (int k = 0; k < 16; k++) {
            float ar[8], br[8];
            #pragma unroll
            for (int i = 0; i < 8; i++) ar[i] = As[k][ty * 8 + i];
            #pragma unroll
            for (int j = 0; j < 8; j++) br[j] = Bs[k][tx * 8 + j];
            #pragma unroll
            for (int i = 0; i < 8; i++)
                #pragma unroll
                for (int j = 0; j < 8; j++) acc[i][j] += ar[i] * br[j];
        }
        __syncthreads();
    }

    #pragma unroll
    for (int i = 0; i < 8; i++) {
        size_t r = (size_t)(bm + ty * 8 + i);
        #pragma unroll
        for (int j = 0; j < 8; j += 4) {
            float4 v = { acc[i][j], acc[i][j+1], acc[i][j+2], acc[i][j+3] };
            *(float4*)&C[r * EF + tx * 8 + j] = v;
        }
    }
}

// ---------------- fused GRU cell elementwise --------------------------------
__global__ void __launch_bounds__(256) gru_kernel(
    const float* __restrict__ gi,
    const float* __restrict__ gh,
    const float* __restrict__ h,
    float* __restrict__ out_final,
    int last)
{
    size_t idx = (size_t)blockIdx.x * blockDim.x + threadIdx.x;   // 0..1048575
    int i = (int)(idx >> 7), f = (int)(idx & 127);
    const float* gir = gi + (size_t)i * G3F;
    const float* ghr = gh + (size_t)i * G3F;
    float i_r = gir[f], i_z = gir[128 + f], i_n = gir[256 + f];
    float h_r = ghr[f], h_z = ghr[128 + f], h_n = ghr[256 + f];
    float hv  = h[idx];
    float r = 1.0f / (1.0f + expf(-(i_r + h_r)));
    float z = 1.0f / (1.0f + expf(-(i_z + h_z)));
    float n = tanhf(i_n + r * h_n);
    float nh = (1.0f - z) * n + z * hv;
    if (last) out_final[idx] = nh;
    else      h_buf[idx] = nh;
}

// ---------------- launch ----------------------------------------------------
extern "C" void kernel_launch(void* const* d_in, const int* in_sizes, int n_in,
                              void* d_out, int out_size)
{
    const float* feats  = (const float*)d_in[0];
    const int*   graphs = (const int*)d_in[1];         // int32 (JAX default)
    const float* fc_w   = (const float*)d_in[2];       // (4,128,128) -> (512,128)
    const float* fc_b   = (const float*)d_in[3];       // (4,128) -> (512,)
    const float* tw     = (const float*)d_in[4];
    const float* w_ih   = (const float*)d_in[5];       // (384,512)
    const float* w_hh   = (const float*)d_in[6];       // (384,128)
    const float* b_ih   = (const float*)d_in[7];
    const float* b_hh   = (const float*)d_in[8];
    float*       out    = (float*)d_out;

    float *g_p, *a_p, *x_p, *gi_p, *gh_p, *h_p;
    cudaGetSymbolAddress((void**)&g_p,  g_buf);
    cudaGetSymbolAddress((void**)&a_p,  a_buf);
    cudaGetSymbolAddress((void**)&x_p,  x_buf);
    cudaGetSymbolAddress((void**)&gi_p, gi_buf);
    cudaGetSymbolAddress((void**)&gh_p, gh_buf);
    cudaGetSymbolAddress((void**)&h_p,  h_buf);

    // One-time per launch: scaled graph (loop-invariant) + initial hidden state
    {
        size_t total = (size_t)Bsz * Ee * Nn * Nn;          // 33,554,432
        convert_g_kernel<<<(unsigned)(total / (256 * 4)), 256>>>(graphs, tw, g_p);
        copy_h_kernel<<<(MROWS * Ff) / 256, 256>>>(feats, h_p);
    }

    for (int s = 0; s < NSTEPS; s++) {
        // a2d = h @ fc_w^T + fc_b   (8192 x 512, K=128)
        {
            dim3 grid(MROWS / 128, EF / 128);
            sgemm_nt_kernel<<<grid, 256>>>(h_p, Ff, fc_w, fc_b, a_p, EF, Ff);
        }
        // flows = g @ a   (batched 32 x [1024x1024 @ 1024x128])
        {
            dim3 grid(Nn / 128, 1, Bsz * Ee);
            sgemm_flows_kernel<<<grid, 256>>>(g_p, a_p, x_p);
        }
        // gi = x @ w_ih^T + b_ih   (8192 x 384, K=512)
        {
            dim3 grid(MROWS / 128, G3F / 128);
            sgemm_nt_kernel<<<grid, 256>>>(x_p, EF, w_ih, b_ih, gi_p, G3F, EF);
        }
        // gh = h @ w_hh^T + b_hh   (8192 x 384, K=128)
        {
            dim3 grid(MROWS / 128, G3F / 128);
            sgemm_nt_kernel<<<grid, 256>>>(h_p, Ff, w_hh, b_hh, gh_p, G3F, Ff);
        }
        // GRU cell (in-place on h; final step writes d_out)
        gru_kernel<<<(MROWS * Ff) / 256, 256>>>(gi_p, gh_p, h_p, out,
                                                (s == NSTEPS - 1) ? 1 : 0);
    }
}

// round 5
// speedup vs baseline: 1.5648x; 1.5648x over previous
#include <cuda_runtime.h>
#include <cuda_bf16.h>
#include <math.h>
#include <cstdint>

// Problem constants (fixed by the dataset)
#define Bsz 8
#define Nn  1024
#define Ff  128
#define Ee  4
#define NSTEPS 5

#define MROWS (Bsz * Nn)       // 8192
#define EF    (Ee * Ff)        // 512
#define G3F   (3 * Ff)         // 384

// ---------------- scratch (device globals: no allocations allowed) ----------
__device__ __nv_bfloat16 mask_bf [(size_t)Bsz * Ee * Nn * Nn];  // 64MB, {0,1}
__device__ __nv_bfloat16 ahiT_buf[(size_t)Bsz * Ee * Ff * Nn];  // [z][f][m] 8MB
__device__ __nv_bfloat16 aloT_buf[(size_t)Bsz * Ee * Ff * Nn];  // [z][f][m] 8MB
__device__ float a_buf [(size_t)MROWS * EF];
__device__ float x_buf [(size_t)MROWS * EF];
__device__ float gi_buf[(size_t)MROWS * G3F];
__device__ float gh_buf[(size_t)MROWS * G3F];
__device__ float h_buf [(size_t)MROWS * Ff];

__device__ __forceinline__ uint32_t smem_to_u32(const void* smem_ptr) {
    uint32_t addr;
    asm("{ .reg .u64 tmp; cvta.to.shared.u64 tmp, %1; cvt.u32.u64 %0, tmp; }"
        : "=r"(addr) : "l"(smem_ptr));
    return addr;
}

// ---------------- one-time: mask -> bf16 {0,1} ------------------------------
__global__ void __launch_bounds__(256) convert_mask_kernel(
    const int* __restrict__ graphs, __nv_bfloat16* __restrict__ mask)
{
    size_t idx4 = ((size_t)blockIdx.x * blockDim.x + threadIdx.x) * 4;
    int4 gv = *(const int4*)&graphs[idx4];
    __nv_bfloat16 o[4];
    o[0] = __float2bfloat16((float)gv.x);
    o[1] = __float2bfloat16((float)gv.y);
    o[2] = __float2bfloat16((float)gv.z);
    o[3] = __float2bfloat16((float)gv.w);
    *(uint2*)&mask[idx4] = *(uint2*)o;
}

__global__ void __launch_bounds__(256) copy_h_kernel(
    const float* __restrict__ src, float* __restrict__ dst)
{
    size_t idx = (size_t)blockIdx.x * blockDim.x + threadIdx.x;
    dst[idx] = src[idx];
}

// ---------------- per-step: a' = w_e * a2d, split hi/lo, transpose ----------
// a2d (8192 x 512) fp32 -> ahiT/aloT [z=b*4+e][f][m] bf16
__global__ void __launch_bounds__(256) convert_a_kernel(
    const float* __restrict__ a2d, const float* __restrict__ tw,
    __nv_bfloat16* __restrict__ hiT, __nv_bfloat16* __restrict__ loT)
{
    __shared__ float t[32][129];
    const int z = blockIdx.y;
    const int b = z >> 2, e = z & 3;
    const int m0 = blockIdx.x * 32;
    const float w = 1.0f / (1.0f + expf(-tw[e]));
    const int tid = threadIdx.x;

    #pragma unroll
    for (int i = 0; i < 16; i++) {
        int idx = tid + i * 256;
        int row = idx >> 7;           // m within tile, 0..31
        int f   = idx & 127;
        t[row][f] = a2d[((size_t)(b * Nn + m0 + row)) * EF + e * Ff + f] * w;
    }
    __syncthreads();

    const int f    = tid >> 1;        // 0..127
    const int half = tid & 1;         // 0,1
    const int ms   = half * 16;
    __nv_bfloat16 ho[16], lo[16];
    #pragma unroll
    for (int j = 0; j < 16; j++) {
        float v = t[ms + j][f];
        __nv_bfloat16 h = __float2bfloat16(v);
        ho[j] = h;
        lo[j] = __float2bfloat16(v - __bfloat162float(h));
    }
    size_t base = (size_t)z * (Ff * Nn) + (size_t)f * Nn + m0 + ms;
    *(uint4*)&hiT[base]     = *(uint4*)&ho[0];
    *(uint4*)&hiT[base + 8] = *(uint4*)&ho[8];
    *(uint4*)&loT[base]     = *(uint4*)&lo[0];
    *(uint4*)&loT[base + 8] = *(uint4*)&lo[8];
}

// ---------------- flows via mma.sync bf16 (HMMA, sm_100 baseline ISA) -------
// Per CTA (z, bm): C[128 n x 128 f] = sum_m mask[z][bm+n][m] * (hi+lo)T[z][f][m]
// 8 warps: wm in {0,1} (64 rows each), wn in {0..3} (32 cols each).
// K-chunks of 64; SMEM rows padded to 72 bf16 (144B) for conflict-free ldmatrix.
#define FLW_STRIDE 72
#define FLW_TILEB  (128 * FLW_STRIDE * 2)      // 18432 bytes per tile
#define FLW_SMEM   (3 * FLW_TILEB)             // 55296 bytes

__device__ __forceinline__ void ldsm_x4(uint32_t* r, uint32_t addr) {
    asm volatile("ldmatrix.sync.aligned.m8n8.x4.shared.b16 {%0,%1,%2,%3}, [%4];"
        : "=r"(r[0]), "=r"(r[1]), "=r"(r[2]), "=r"(r[3]) : "r"(addr));
}
__device__ __forceinline__ void ldsm_x2(uint32_t* r, uint32_t addr) {
    asm volatile("ldmatrix.sync.aligned.m8n8.x2.shared.b16 {%0,%1}, [%2];"
        : "=r"(r[0]), "=r"(r[1]) : "r"(addr));
}
__device__ __forceinline__ void mma_bf16(float* c, const uint32_t* a, const uint32_t* b) {
    asm volatile(
        "mma.sync.aligned.m16n8k16.row.col.f32.bf16.bf16.f32 "
        "{%0,%1,%2,%3}, {%4,%5,%6,%7}, {%8,%9}, {%0,%1,%2,%3};"
        : "+f"(c[0]), "+f"(c[1]), "+f"(c[2]), "+f"(c[3])
        : "r"(a[0]), "r"(a[1]), "r"(a[2]), "r"(a[3]), "r"(b[0]), "r"(b[1]));
}

__global__ void __launch_bounds__(256) flows_hmma_kernel(
    const __nv_bfloat16* __restrict__ mask,
    const __nv_bfloat16* __restrict__ hiT,
    const __nv_bfloat16* __restrict__ loT,
    float* __restrict__ Xm)
{
    extern __shared__ char smem[];
    __nv_bfloat16* sA = (__nv_bfloat16*)smem;
    const uint32_t su = smem_to_u32(smem);

    const int tid  = threadIdx.x;
    const int wid  = tid >> 5, lane = tid & 31;
    const int wm   = wid & 1;          // 0..1 -> n-rows 64 each
    const int wn   = wid >> 1;         // 0..3 -> f-cols 32 each
    const int z    = blockIdx.y;
    const int bm   = blockIdx.x * 128;

    const __nv_bfloat16* Asrc = mask + ((size_t)z << 20) + ((size_t)bm << 10);
    const __nv_bfloat16* Hsrc = hiT + (size_t)z * (Ff * Nn);
    const __nv_bfloat16* Lsrc = loT + (size_t)z * (Ff * Nn);

    float acc[4][4][4];
    #pragma unroll
    for (int i = 0; i < 4; i++)
        #pragma unroll
        for (int j = 0; j < 4; j++)
            #pragma unroll
            for (int k = 0; k < 4; k++) acc[i][j][k] = 0.0f;

    // ldmatrix per-lane address components
    const int a_row_l = (lane & 7) + ((lane >> 3) & 1) * 8;   // row within 16-row frag
    const int a_kbyte = ((lane >> 4) & 1) * 16;               // 0 or 16 bytes (k half)
    const int bl_     = lane & 15;
    const int b_row_l = bl_ & 7;                              // row within 8-row frag
    const int b_kbyte = (bl_ >> 3) * 16;

    for (int c = 0; c < 16; c++) {
        const int k0 = c * 64;
        __syncthreads();   // previous chunk's compute done before overwrite
        #pragma unroll
        for (int i = 0; i < 4; i++) {
            int idx = tid + i * 256;          // 0..1023
            int row = idx >> 3;
            int cg  = (idx & 7) * 8;          // bf16 col
            uint32_t so = (uint32_t)(row * FLW_STRIDE + cg);
            *(uint4*)(sA + so) =
                *(const uint4*)(Asrc + (size_t)row * Nn + k0 + cg);
            *(uint4*)((__nv_bfloat16*)(smem + FLW_TILEB) + so) =
                *(const uint4*)(Hsrc + (size_t)row * Nn + k0 + cg);
            *(uint4*)((__nv_bfloat16*)(smem + 2 * FLW_TILEB) + so) =
                *(const uint4*)(Lsrc + (size_t)row * Nn + k0 + cg);
        }
        __syncthreads();

        #pragma unroll
        for (int ks = 0; ks < 4; ks++) {
            uint32_t af[4][4];
            #pragma unroll
            for (int mf = 0; mf < 4; mf++) {
                uint32_t addr = su
                    + (uint32_t)((wm * 64 + mf * 16 + a_row_l) * (FLW_STRIDE * 2))
                    + (uint32_t)(ks * 32 + a_kbyte);
                ldsm_x4(af[mf], addr);
            }
            uint32_t bh[4][2], bl[4][2];
            #pragma unroll
            for (int nf = 0; nf < 4; nf++) {
                uint32_t rowb = (uint32_t)(wn * 32 + nf * 8 + b_row_l);
                uint32_t addr = su + FLW_TILEB
                    + rowb * (FLW_STRIDE * 2) + (uint32_t)(ks * 32 + b_kbyte);
                ldsm_x2(bh[nf], addr);
                ldsm_x2(bl[nf], addr + FLW_TILEB);
            }
            #pragma unroll
            for (int mf = 0; mf < 4; mf++)
                #pragma unroll
                for (int nf = 0; nf < 4; nf++) {
                    mma_bf16(acc[mf][nf], af[mf], bh[nf]);
                    mma_bf16(acc[mf][nf], af[mf], bl[nf]);
                }
        }
    }

    // Epilogue: C[n][f] fragments -> Xm[(b*Nn+n)*EF + e*128 + f]
    const int b = z >> 2, e = z & 3;
    const int qr = lane >> 2;              // 0..7
    const int qc = (lane & 3) * 2;         // 0,2,4,6
    #pragma unroll
    for (int mf = 0; mf < 4; mf++) {
        #pragma unroll
        for (int nf = 0; nf < 4; nf++) {
            int n0 = bm + wm * 64 + mf * 16 + qr;
            int f0 = wn * 32 + nf * 8 + qc;
            float2 v0 = { acc[mf][nf][0], acc[mf][nf][1] };
            float2 v1 = { acc[mf][nf][2], acc[mf][nf][3] };
            *(float2*)(Xm + ((size_t)(b * Nn + n0)) * EF + e * Ff + f0)     = v0;
            *(float2*)(Xm + ((size_t)(b * Nn + n0 + 8)) * EF + e * Ff + f0) = v1;
        }
    }
}

// ---------------- generic NT SGEMM:  C = A(MxK) * B(NxK)^T + bias ------------
__global__ void __launch_bounds__(256) sgemm_nt_kernel(
    const float* __restrict__ A, int lda,
    const float* __restrict__ B,
    const float* __restrict__ bias,
    float* __restrict__ C, int ldc,
    int K)
{
    __shared__ float As[16][128];
    __shared__ float Bs[16][128];

    const int bm = blockIdx.x * 128;
    const int bn = blockIdx.y * 128;
    const int tid = threadIdx.x;

    const int l_row = tid >> 2;
    const int l_col = (tid & 3) * 4;
    const int ty = tid >> 4;
    const int tx = tid & 15;

    float acc[8][8];
    #pragma unroll
    for (int i = 0; i < 8; i++)
        #pragma unroll
        for (int j = 0; j < 8; j++) acc[i][j] = 0.0f;

    for (int k0 = 0; k0 < K; k0 += 16) {
        #pragma unroll
        for (int it = 0; it < 2; it++) {
            int r = l_row + it * 64;
            float4 v = *(const float4*)&A[(size_t)(bm + r) * lda + k0 + l_col];
            As[l_col + 0][r] = v.x; As[l_col + 1][r] = v.y;
            As[l_col + 2][r] = v.z; As[l_col + 3][r] = v.w;
        }
        #pragma unroll
        for (int it = 0; it < 2; it++) {
            int r = l_row + it * 64;
            float4 v = *(const float4*)&B[(size_t)(bn + r) * K + k0 + l_col];
            Bs[l_col + 0][r] = v.x; Bs[l_col + 1][r] = v.y;
            Bs[l_col + 2][r] = v.z; Bs[l_col + 3][r] = v.w;
        }
        __syncthreads();

        #pragma unroll
        for (int k = 0; k < 16; k++) {
            float ar[8], br[8];
            #pragma unroll
            for (int i = 0; i < 8; i++) ar[i] = As[k][ty * 8 + i];
            #pragma unroll
            for (int j = 0; j < 8; j++) br[j] = Bs[k][tx * 8 + j];
            #pragma unroll
            for (int i = 0; i < 8; i++)
                #pragma unroll
                for (int j = 0; j < 8; j++) acc[i][j] += ar[i] * br[j];
        }
        __syncthreads();
    }

    #pragma unroll
    for (int i = 0; i < 8; i++) {
        size_t r = (size_t)(bm + ty * 8 + i);
        #pragma unroll
        for (int j = 0; j < 8; j += 4) {
            int c = tx * 8 + j;
            float4 v;
            v.x = acc[i][j + 0] + bias[bn + c + 0];
            v.y = acc[i][j + 1] + bias[bn + c + 1];
            v.z = acc[i][j + 2] + bias[bn + c + 2];
            v.w = acc[i][j + 3] + bias[bn + c + 3];
            *(float4*)&C[r * ldc + bn + c] = v;
        }
    }
}

// ---------------- fused GRU cell elementwise --------------------------------
__global__ void __launch_bounds__(256) gru_kernel(
    const float* __restrict__ gi,
    const float* __restrict__ gh,
    const float* __restrict__ h,
    float* __restrict__ out_final,
    int last)
{
    size_t idx = (size_t)blockIdx.x * blockDim.x + threadIdx.x;
    int i = (int)(idx >> 7), f = (int)(idx & 127);
    const float* gir = gi + (size_t)i * G3F;
    const float* ghr = gh + (size_t)i * G3F;
    float i_r = gir[f], i_z = gir[128 + f], i_n = gir[256 + f];
    float h_r = ghr[f], h_z = ghr[128 + f], h_n = ghr[256 + f];
    float hv  = h[idx];
    float r = 1.0f / (1.0f + expf(-(i_r + h_r)));
    float z = 1.0f / (1.0f + expf(-(i_z + h_z)));
    float n = tanhf(i_n + r * h_n);
    float nh = (1.0f - z) * n + z * hv;
    if (last) out_final[idx] = nh;
    else      h_buf[idx] = nh;
}

// ---------------- launch ----------------------------------------------------
extern "C" void kernel_launch(void* const* d_in, const int* in_sizes, int n_in,
                              void* d_out, int out_size)
{
    const float* feats  = (const float*)d_in[0];
    const int*   graphs = (const int*)d_in[1];         // int32 (JAX default)
    const float* fc_w   = (const float*)d_in[2];       // (512,128)
    const float* fc_b   = (const float*)d_in[3];       // (512,)
    const float* tw     = (const float*)d_in[4];
    const float* w_ih   = (const float*)d_in[5];       // (384,512)
    const float* w_hh   = (const float*)d_in[6];       // (384,128)
    const float* b_ih   = (const float*)d_in[7];
    const float* b_hh   = (const float*)d_in[8];
    float*       out    = (float*)d_out;

    __nv_bfloat16 *mask_p, *hiT_p, *loT_p;
    float *a_p, *x_p, *gi_p, *gh_p, *h_p;
    cudaGetSymbolAddress((void**)&mask_p, mask_bf);
    cudaGetSymbolAddress((void**)&hiT_p,  ahiT_buf);
    cudaGetSymbolAddress((void**)&loT_p,  aloT_buf);
    cudaGetSymbolAddress((void**)&a_p,  a_buf);
    cudaGetSymbolAddress((void**)&x_p,  x_buf);
    cudaGetSymbolAddress((void**)&gi_p, gi_buf);
    cudaGetSymbolAddress((void**)&gh_p, gh_buf);
    cudaGetSymbolAddress((void**)&h_p,  h_buf);

    cudaFuncSetAttribute(flows_hmma_kernel,
                         cudaFuncAttributeMaxDynamicSharedMemorySize, FLW_SMEM);

    // One-time per launch
    {
        size_t total = (size_t)Bsz * Ee * Nn * Nn;   // 33,554,432
        convert_mask_kernel<<<(unsigned)(total / (256 * 4)), 256>>>(graphs, mask_p);
        copy_h_kernel<<<(MROWS * Ff) / 256, 256>>>(feats, h_p);
    }

    for (int s = 0; s < NSTEPS; s++) {
        // a2d = h @ fc_w^T + fc_b   (8192 x 512, K=128)
        {
            dim3 grid(MROWS / 128, EF / 128);
            sgemm_nt_kernel<<<grid, 256>>>(h_p, Ff, fc_w, fc_b, a_p, EF, Ff);
        }
        // a' = w_e*a2d, hi/lo split + transpose -> [z][f][m]
        {
            dim3 grid(Nn / 32, Bsz * Ee);
            convert_a_kernel<<<grid, 256>>>(a_p, tw, hiT_p, loT_p);
        }
        // flows = mask @ a'  via mma.sync bf16 (32 batches x [1024x1024x128], hi+lo)
        {
            dim3 grid(Nn / 128, Bsz * Ee);
            flows_hmma_kernel<<<grid, 256, FLW_SMEM>>>(mask_p, hiT_p, loT_p, x_p);
        }
        // gi = x @ w_ih^T + b_ih   (8192 x 384, K=512)
        {
            dim3 grid(MROWS / 128, G3F / 128);
            sgemm_nt_kernel<<<grid, 256>>>(x_p, EF, w_ih, b_ih, gi_p, G3F, EF);
        }
        // gh = h @ w_hh^T + b_hh   (8192 x 384, K=128)
        {
            dim3 grid(MROWS / 128, G3F / 128);
            sgemm_nt_kernel<<<grid, 256>>>(h_p, Ff, w_hh, b_hh, gh_p, G3F, Ff);
        }
        // GRU cell
        gru_kernel<<<(MROWS * Ff) / 256, 256>>>(gi_p, gh_p, h_p, out,
                                                (s == NSTEPS - 1) ? 1 : 0);
    }
}

// round 9
// speedup vs baseline: 1.6259x; 1.0391x over previous
#include <cuda_runtime.h>
#include <cuda_bf16.h>
#include <math.h>
#include <cstdint>

// Problem constants (fixed by the dataset)
#define Bsz 8
#define Nn  1024
#define Ff  128
#define Ee  4
#define NSTEPS 5

#define MROWS (Bsz * Nn)       // 8192
#define EF    (Ee * Ff)        // 512
#define G3F   (3 * Ff)         // 384

// ---------------- scratch (device globals: no allocations allowed) ----------
__device__ __nv_bfloat16 mask_bf [(size_t)Bsz * Ee * Nn * Nn];  // 64MB, {0,1}
__device__ __nv_bfloat16 ahiT_buf[(size_t)Bsz * Ee * Ff * Nn];  // [z][f][m] 8MB
__device__ __nv_bfloat16 aloT_buf[(size_t)Bsz * Ee * Ff * Nn];  // [z][f][m] 8MB
__device__ float a_buf [(size_t)MROWS * EF];
__device__ float x_buf [(size_t)MROWS * EF];
__device__ float gi_buf[(size_t)MROWS * G3F];
__device__ float gh_buf[(size_t)MROWS * G3F];
__device__ float h_buf [(size_t)MROWS * Ff];

__device__ __forceinline__ uint32_t smem_to_u32(const void* smem_ptr) {
    uint32_t addr;
    asm("{ .reg .u64 tmp; cvta.to.shared.u64 tmp, %1; cvt.u32.u64 %0, tmp; }"
        : "=r"(addr) : "l"(smem_ptr));
    return addr;
}

// ---------------- cp.async helpers (sm_80+ baseline ISA) --------------------
__device__ __forceinline__ void cp_async16(uint32_t smem_addr, const void* gptr) {
    asm volatile("cp.async.cg.shared.global [%0], [%1], 16;"
        :: "r"(smem_addr), "l"(gptr));
}
__device__ __forceinline__ void cp_commit() {
    asm volatile("cp.async.commit_group;" ::: "memory");
}
template<int N> __device__ __forceinline__ void cp_wait() {
    asm volatile("cp.async.wait_group %0;" :: "n"(N) : "memory");
}

// ---------------- one-time: mask -> bf16 {0,1} ------------------------------
__global__ void __launch_bounds__(256) convert_mask_kernel(
    const int* __restrict__ graphs, __nv_bfloat16* __restrict__ mask)
{
    size_t idx4 = ((size_t)blockIdx.x * blockDim.x + threadIdx.x) * 4;
    int4 gv = *(const int4*)&graphs[idx4];
    __nv_bfloat16 o[4];
    o[0] = __float2bfloat16((float)gv.x);
    o[1] = __float2bfloat16((float)gv.y);
    o[2] = __float2bfloat16((float)gv.z);
    o[3] = __float2bfloat16((float)gv.w);
    *(uint2*)&mask[idx4] = *(uint2*)o;
}

__global__ void __launch_bounds__(256) copy_h_kernel(
    const float* __restrict__ src, float* __restrict__ dst)
{
    size_t idx = (size_t)blockIdx.x * blockDim.x + threadIdx.x;
    dst[idx] = src[idx];
}

// ---------------- per-step: a' = w_e * a2d, split hi/lo, transpose ----------
__global__ void __launch_bounds__(256) convert_a_kernel(
    const float* __restrict__ a2d, const float* __restrict__ tw,
    __nv_bfloat16* __restrict__ hiT, __nv_bfloat16* __restrict__ loT)
{
    __shared__ float t[32][129];
    const int z = blockIdx.y;
    const int b = z >> 2, e = z & 3;
    const int m0 = blockIdx.x * 32;
    const float w = 1.0f / (1.0f + expf(-tw[e]));
    const int tid = threadIdx.x;

    #pragma unroll
    for (int i = 0; i < 16; i++) {
        int idx = tid + i * 256;
        int row = idx >> 7;
        int f   = idx & 127;
        t[row][f] = a2d[((size_t)(b * Nn + m0 + row)) * EF + e * Ff + f] * w;
    }
    __syncthreads();

    const int f    = tid >> 1;
    const int half = tid & 1;
    const int ms   = half * 16;
    __nv_bfloat16 ho[16], lo[16];
    #pragma unroll
    for (int j = 0; j < 16; j++) {
        float v = t[ms + j][f];
        __nv_bfloat16 h = __float2bfloat16(v);
        ho[j] = h;
        lo[j] = __float2bfloat16(v - __bfloat162float(h));
    }
    size_t base = (size_t)z * (Ff * Nn) + (size_t)f * Nn + m0 + ms;
    *(uint4*)&hiT[base]     = *(uint4*)&ho[0];
    *(uint4*)&hiT[base + 8] = *(uint4*)&ho[8];
    *(uint4*)&loT[base]     = *(uint4*)&lo[0];
    *(uint4*)&loT[base + 8] = *(uint4*)&lo[8];
}

// ---------------- mma helpers ------------------------------------------------
__device__ __forceinline__ void ldsm_x4(uint32_t* r, uint32_t addr) {
    asm volatile("ldmatrix.sync.aligned.m8n8.x4.shared.b16 {%0,%1,%2,%3}, [%4];"
        : "=r"(r[0]), "=r"(r[1]), "=r"(r[2]), "=r"(r[3]) : "r"(addr));
}
__device__ __forceinline__ void ldsm_x2(uint32_t* r, uint32_t addr) {
    asm volatile("ldmatrix.sync.aligned.m8n8.x2.shared.b16 {%0,%1}, [%2];"
        : "=r"(r[0]), "=r"(r[1]) : "r"(addr));
}
__device__ __forceinline__ void mma_bf16(float* c, const uint32_t* a, const uint32_t* b) {
    asm volatile(
        "mma.sync.aligned.m16n8k16.row.col.f32.bf16.bf16.f32 "
        "{%0,%1,%2,%3}, {%4,%5,%6,%7}, {%8,%9}, {%0,%1,%2,%3};"
        : "+f"(c[0]), "+f"(c[1]), "+f"(c[2]), "+f"(c[3])
        : "r"(a[0]), "r"(a[1]), "r"(a[2]), "r"(a[3]), "r"(b[0]), "r"(b[1]));
}

#define FLW_STRIDE 72
#define FLW_TILEB  (128 * FLW_STRIDE * 2)      // 18432 bytes per tile
#define FLW_STAGE  (3 * FLW_TILEB)             // 55296 bytes (A, Bhi, Blo)
#define FLW_SMEM   (2 * FLW_STAGE)             // 110592 bytes, 2-stage pipeline

// ---------------- flows via mma.sync bf16, cp.async 2-stage pipeline --------
// Per CTA (z, bm): X[128 n x 128 f] = sum_m mask[z][bm+n][m] * (hi+lo)T[z][f][m]
__global__ void __launch_bounds__(256) flows_hmma_kernel(
    const __nv_bfloat16* __restrict__ mask,
    const __nv_bfloat16* __restrict__ hiT,
    const __nv_bfloat16* __restrict__ loT,
    float* __restrict__ Xm)
{
    extern __shared__ char smem[];
    const uint32_t su = smem_to_u32(smem);

    const int tid  = threadIdx.x;
    const int wid  = tid >> 5, lane = tid & 31;
    const int wm   = wid & 1;          // 0..1 -> n-rows 64 each
    const int wn   = wid >> 1;         // 0..3 -> f-cols 32 each
    const int z    = blockIdx.y;
    const int bm   = blockIdx.x * 128;

    const __nv_bfloat16* Asrc = mask + ((size_t)z << 20) + ((size_t)bm << 10);
    const __nv_bfloat16* Hsrc = hiT + (size_t)z * (Ff * Nn);
    const __nv_bfloat16* Lsrc = loT + (size_t)z * (Ff * Nn);

    // per-thread load geometry (same for all chunks)
    const int l_row = (tid * 4) >> 3;            // unused; explicit below
    (void)l_row;

    float acc[4][4][4];
    #pragma unroll
    for (int i = 0; i < 4; i++)
        #pragma unroll
        for (int j = 0; j < 4; j++)
            #pragma unroll
            for (int k = 0; k < 4; k++) acc[i][j][k] = 0.0f;

    const int a_row_l = (lane & 7) + ((lane >> 3) & 1) * 8;
    const int a_kbyte = ((lane >> 4) & 1) * 16;
    const int bl_     = lane & 15;
    const int b_row_l = bl_ & 7;
    const int b_kbyte = (bl_ >> 3) * 16;

    // ---- prologue: issue chunk 0 into stage 0
    {
        const int k0 = 0;
        const uint32_t sb = su;
        #pragma unroll
        for (int i = 0; i < 4; i++) {
            int idx = tid + i * 256;
            int row = idx >> 3;
            int cg  = (idx & 7) * 8;
            uint32_t so = (uint32_t)(row * (FLW_STRIDE * 2) + cg * 2);
            cp_async16(sb + so,                 Asrc + (size_t)row * Nn + k0 + cg);
            cp_async16(sb + FLW_TILEB + so,     Hsrc + (size_t)row * Nn + k0 + cg);
            cp_async16(sb + 2 * FLW_TILEB + so, Lsrc + (size_t)row * Nn + k0 + cg);
        }
        cp_commit();
    }

    for (int c = 0; c < 16; c++) {
        if (c < 15) {
            const int k0 = (c + 1) * 64;
            const uint32_t sb = su + ((c + 1) & 1) * FLW_STAGE;
            #pragma unroll
            for (int i = 0; i < 4; i++) {
                int idx = tid + i * 256;
                int row = idx >> 3;
                int cg  = (idx & 7) * 8;
                uint32_t so = (uint32_t)(row * (FLW_STRIDE * 2) + cg * 2);
                cp_async16(sb + so,                 Asrc + (size_t)row * Nn + k0 + cg);
                cp_async16(sb + FLW_TILEB + so,     Hsrc + (size_t)row * Nn + k0 + cg);
                cp_async16(sb + 2 * FLW_TILEB + so, Lsrc + (size_t)row * Nn + k0 + cg);
            }
            cp_commit();
            cp_wait<1>();          // chunk c's group complete
        } else {
            cp_wait<0>();
        }
        __syncthreads();

        const uint32_t stg = su + (c & 1) * FLW_STAGE;
        #pragma unroll
        for (int ks = 0; ks < 4; ks++) {
            uint32_t af[4][4];
            #pragma unroll
            for (int mf = 0; mf < 4; mf++) {
                uint32_t addr = stg
                    + (uint32_t)((wm * 64 + mf * 16 + a_row_l) * (FLW_STRIDE * 2))
                    + (uint32_t)(ks * 32 + a_kbyte);
                ldsm_x4(af[mf], addr);
            }
            uint32_t bh[4][2], bl[4][2];
            #pragma unroll
            for (int nf = 0; nf < 4; nf++) {
                uint32_t rowb = (uint32_t)(wn * 32 + nf * 8 + b_row_l);
                uint32_t addr = stg + FLW_TILEB
                    + rowb * (FLW_STRIDE * 2) + (uint32_t)(ks * 32 + b_kbyte);
                ldsm_x2(bh[nf], addr);
                ldsm_x2(bl[nf], addr + FLW_TILEB);
            }
            #pragma unroll
            for (int mf = 0; mf < 4; mf++)
                #pragma unroll
                for (int nf = 0; nf < 4; nf++) {
                    mma_bf16(acc[mf][nf], af[mf], bh[nf]);
                    mma_bf16(acc[mf][nf], af[mf], bl[nf]);
                }
        }
        __syncthreads();           // all warps done with stage before reuse
    }

    // Epilogue: fp32 X writes (R5-proven path)
    const int b = z >> 2, e = z & 3;
    const int qr = lane >> 2;              // 0..7
    const int qc = (lane & 3) * 2;         // 0,2,4,6
    #pragma unroll
    for (int mf = 0; mf < 4; mf++) {
        #pragma unroll
        for (int nf = 0; nf < 4; nf++) {
            int n0 = bm + wm * 64 + mf * 16 + qr;
            int f0 = wn * 32 + nf * 8 + qc;
            float2 v0 = { acc[mf][nf][0], acc[mf][nf][1] };
            float2 v1 = { acc[mf][nf][2], acc[mf][nf][3] };
            *(float2*)(Xm + ((size_t)(b * Nn + n0)) * EF + e * Ff + f0)     = v0;
            *(float2*)(Xm + ((size_t)(b * Nn + n0 + 8)) * EF + e * Ff + f0) = v1;
        }
    }
}

// ---------------- generic NT SGEMM with register prefetch -------------------
// C = A(MxK) * B(NxK)^T + bias. 128x128x16 tile, 256 threads, 8x8 microtile.
__global__ void __launch_bounds__(256, 2) sgemm_nt_kernel(
    const float* __restrict__ A, int lda,
    const float* __restrict__ B,
    const float* __restrict__ bias,
    float* __restrict__ C, int ldc,
    int K)
{
    __shared__ float As[16][128];
    __shared__ float Bs[16][128];

    const int bm = blockIdx.x * 128;
    const int bn = blockIdx.y * 128;
    const int tid = threadIdx.x;

    const int l_row = tid >> 2;          // 0..63
    const int l_col = (tid & 3) * 4;     // 0,4,8,12
    const int ty = tid >> 4;             // 0..15
    const int tx = tid & 15;             // 0..15

    float acc[8][8];
    #pragma unroll
    for (int i = 0; i < 8; i++)
        #pragma unroll
        for (int j = 0; j < 8; j++) acc[i][j] = 0.0f;

    // prologue fetch (chunk 0) into registers
    float4 av0 = *(const float4*)&A[(size_t)(bm + l_row) * lda + l_col];
    float4 av1 = *(const float4*)&A[(size_t)(bm + l_row + 64) * lda + l_col];
    float4 bv0 = *(const float4*)&B[(size_t)(bn + l_row) * K + l_col];
    float4 bv1 = *(const float4*)&B[(size_t)(bn + l_row + 64) * K + l_col];

    for (int k0 = 0; k0 < K; k0 += 16) {
        // store prefetched chunk to smem (transposed)
        As[l_col + 0][l_row] = av0.x; As[l_col + 1][l_row] = av0.y;
        As[l_col + 2][l_row] = av0.z; As[l_col + 3][l_row] = av0.w;
        As[l_col + 0][l_row + 64] = av1.x; As[l_col + 1][l_row + 64] = av1.y;
        As[l_col + 2][l_row + 64] = av1.z; As[l_col + 3][l_row + 64] = av1.w;
        Bs[l_col + 0][l_row] = bv0.x; Bs[l_col + 1][l_row] = bv0.y;
        Bs[l_col + 2][l_row] = bv0.z; Bs[l_col + 3][l_row] = bv0.w;
        Bs[l_col + 0][l_row + 64] = bv1.x; Bs[l_col + 1][l_row + 64] = bv1.y;
        Bs[l_col + 2][l_row + 64] = bv1.z; Bs[l_col + 3][l_row + 64] = bv1.w;
        __syncthreads();

        // prefetch next chunk (overlaps compute below)
        if (k0 + 16 < K) {
            av0 = *(const float4*)&A[(size_t)(bm + l_row) * lda + k0 + 16 + l_col];
            av1 = *(const float4*)&A[(size_t)(bm + l_row + 64) * lda + k0 + 16 + l_col];
            bv0 = *(const float4*)&B[(size_t)(bn + l_row) * K + k0 + 16 + l_col];
            bv1 = *(const float4*)&B[(size_t)(bn + l_row + 64) * K + k0 + 16 + l_col];
        }

        #pragma unroll
        for (int k = 0; k < 16; k++) {
            float ar[8], br[8];
            #pragma unroll
            for (int i = 0; i < 8; i++) ar[i] = As[k][ty * 8 + i];
            #pragma unroll
            for (int j = 0; j < 8; j++) br[j] = Bs[k][tx * 8 + j];
            #pragma unroll
            for (int i = 0; i < 8; i++)
                #pragma unroll
                for (int j = 0; j < 8; j++) acc[i][j] += ar[i] * br[j];
        }
        __syncthreads();
    }

    #pragma unroll
    for (int i = 0; i < 8; i++) {
        size_t r = (size_t)(bm + ty * 8 + i);
        #pragma unroll
        for (int j = 0; j < 8; j += 4) {
            int c = tx * 8 + j;
            float4 v;
            v.x = acc[i][j + 0] + bias[bn + c + 0];
            v.y = acc[i][j + 1] + bias[bn + c + 1];
            v.z = acc[i][j + 2] + bias[bn + c + 2];
            v.w = acc[i][j + 3] + bias[bn + c + 3];
            *(float4*)&C[r * ldc + bn + c] = v;
        }
    }
}

// ---------------- fused GRU cell elementwise --------------------------------
__global__ void __launch_bounds__(256) gru_kernel(
    const float* __restrict__ gi,
    const float* __restrict__ gh,
    const float* __restrict__ h,
    float* __restrict__ out_final,
    int last)
{
    size_t idx = (size_t)blockIdx.x * blockDim.x + threadIdx.x;
    int i = (int)(idx >> 7), f = (int)(idx & 127);
    const float* gir = gi + (size_t)i * G3F;
    const float* ghr = gh + (size_t)i * G3F;
    float i_r = gir[f], i_z = gir[128 + f], i_n = gir[256 + f];
    float h_r = ghr[f], h_z = ghr[128 + f], h_n = ghr[256 + f];
    float hv  = h[idx];
    float r = 1.0f / (1.0f + expf(-(i_r + h_r)));
    float z = 1.0f / (1.0f + expf(-(i_z + h_z)));
    float n = tanhf(i_n + r * h_n);
    float nh = (1.0f - z) * n + z * hv;
    if (last) out_final[idx] = nh;
    else      h_buf[idx] = nh;
}

// ---------------- launch ----------------------------------------------------
extern "C" void kernel_launch(void* const* d_in, const int* in_sizes, int n_in,
                              void* d_out, int out_size)
{
    const float* feats  = (const float*)d_in[0];
    const int*   graphs = (const int*)d_in[1];         // int32 (JAX default)
    const float* fc_w   = (const float*)d_in[2];       // (512,128)
    const float* fc_b   = (const float*)d_in[3];       // (512,)
    const float* tw     = (const float*)d_in[4];
    const float* w_ih   = (const float*)d_in[5];       // (384,512)
    const float* w_hh   = (const float*)d_in[6];       // (384,128)
    const float* b_ih   = (const float*)d_in[7];
    const float* b_hh   = (const float*)d_in[8];
    float*       out    = (float*)d_out;

    __nv_bfloat16 *mask_p, *hiT_p, *loT_p;
    float *a_p, *x_p, *gi_p, *gh_p, *h_p;
    cudaGetSymbolAddress((void**)&mask_p, mask_bf);
    cudaGetSymbolAddress((void**)&hiT_p,  ahiT_buf);
    cudaGetSymbolAddress((void**)&loT_p,  aloT_buf);
    cudaGetSymbolAddress((void**)&a_p,  a_buf);
    cudaGetSymbolAddress((void**)&x_p,  x_buf);
    cudaGetSymbolAddress((void**)&gi_p, gi_buf);
    cudaGetSymbolAddress((void**)&gh_p, gh_buf);
    cudaGetSymbolAddress((void**)&h_p,  h_buf);

    cudaFuncSetAttribute(flows_hmma_kernel,
                         cudaFuncAttributeMaxDynamicSharedMemorySize, FLW_SMEM);

    // One-time per launch
    {
        size_t total = (size_t)Bsz * Ee * Nn * Nn;   // 33,554,432
        convert_mask_kernel<<<(unsigned)(total / (256 * 4)), 256>>>(graphs, mask_p);
        copy_h_kernel<<<(MROWS * Ff) / 256, 256>>>(feats, h_p);
    }

    for (int s = 0; s < NSTEPS; s++) {
        // a2d = h @ fc_w^T + fc_b   (8192 x 512, K=128)
        {
            dim3 grid(MROWS / 128, EF / 128);
            sgemm_nt_kernel<<<grid, 256>>>(h_p, Ff, fc_w, fc_b, a_p, EF, Ff);
        }
        // a' = w_e*a2d, hi/lo split + transpose -> [z][f][m]
        {
            dim3 grid(Nn / 32, Bsz * Ee);
            convert_a_kernel<<<grid, 256>>>(a_p, tw, hiT_p, loT_p);
        }
        // flows = mask @ a'  via mma.sync bf16, cp.async pipelined
        {
            dim3 grid(Nn / 128, Bsz * Ee);
            flows_hmma_kernel<<<grid, 256, FLW_SMEM>>>(mask_p, hiT_p, loT_p, x_p);
        }
        // gi = x @ w_ih^T + b_ih   (8192 x 384, K=512)
        {
            dim3 grid(MROWS / 128, G3F / 128);
            sgemm_nt_kernel<<<grid, 256>>>(x_p, EF, w_ih, b_ih, gi_p, G3F, EF);
        }
        // gh = h @ w_hh^T + b_hh   (8192 x 384, K=128)
        {
            dim3 grid(MROWS / 128, G3F / 128);
            sgemm_nt_kernel<<<grid, 256>>>(h_p, Ff, w_hh, b_hh, gh_p, G3F, Ff);
        }
        // GRU cell
        gru_kernel<<<(MROWS * Ff) / 256, 256>>>(gi_p, gh_p, h_p, out,
                                                (s == NSTEPS - 1) ? 1 : 0);
    }
}

// round 10
// speedup vs baseline: 1.6684x; 1.0261x over previous
#include <cuda_runtime.h>
#include <cuda_bf16.h>
#include <math.h>
#include <cstdint>

// Problem constants (fixed by the dataset)
#define Bsz 8
#define Nn  1024
#define Ff  128
#define Ee  4
#define NSTEPS 5

#define MROWS (Bsz * Nn)       // 8192
#define EF    (Ee * Ff)        // 512
#define G3F   (3 * Ff)         // 384

// ---------------- scratch (device globals: no allocations allowed) ----------
__device__ __nv_bfloat16 mask_bf [(size_t)Bsz * Ee * Nn * Nn];  // 64MB, {0,1}
__device__ __nv_bfloat16 ahiT_buf[(size_t)Bsz * Ee * Ff * Nn];  // [z][f][m] 8MB
__device__ __nv_bfloat16 aloT_buf[(size_t)Bsz * Ee * Ff * Nn];  // [z][f][m] 8MB
__device__ float a_buf [(size_t)MROWS * EF];
__device__ float x_buf [(size_t)MROWS * EF];
__device__ float gi_buf[(size_t)MROWS * G3F];
__device__ float gh_buf[(size_t)MROWS * G3F];
__device__ float h_buf [(size_t)MROWS * Ff];

__device__ __forceinline__ uint32_t smem_to_u32(const void* smem_ptr) {
    uint32_t addr;
    asm("{ .reg .u64 tmp; cvta.to.shared.u64 tmp, %1; cvt.u32.u64 %0, tmp; }"
        : "=r"(addr) : "l"(smem_ptr));
    return addr;
}

// ---------------- cp.async helpers (sm_80+ baseline ISA) --------------------
__device__ __forceinline__ void cp_async16(uint32_t smem_addr, const void* gptr) {
    asm volatile("cp.async.cg.shared.global [%0], [%1], 16;"
        :: "r"(smem_addr), "l"(gptr));
}
__device__ __forceinline__ void cp_commit() {
    asm volatile("cp.async.commit_group;" ::: "memory");
}
template<int N> __device__ __forceinline__ void cp_wait() {
    asm volatile("cp.async.wait_group %0;" :: "n"(N) : "memory");
}

// ---------------- one-time: mask -> bf16 {0,1} ------------------------------
__global__ void __launch_bounds__(256) convert_mask_kernel(
    const int* __restrict__ graphs, __nv_bfloat16* __restrict__ mask)
{
    size_t idx4 = ((size_t)blockIdx.x * blockDim.x + threadIdx.x) * 4;
    int4 gv = *(const int4*)&graphs[idx4];
    __nv_bfloat16 o[4];
    o[0] = __float2bfloat16((float)gv.x);
    o[1] = __float2bfloat16((float)gv.y);
    o[2] = __float2bfloat16((float)gv.z);
    o[3] = __float2bfloat16((float)gv.w);
    *(uint2*)&mask[idx4] = *(uint2*)o;
}

__global__ void __launch_bounds__(256) copy_h_kernel(
    const float* __restrict__ src, float* __restrict__ dst)
{
    size_t idx = (size_t)blockIdx.x * blockDim.x + threadIdx.x;
    dst[idx] = src[idx];
}

// ---------------- per-step: a' = w_e * a2d, split hi/lo, transpose ----------
__global__ void __launch_bounds__(256) convert_a_kernel(
    const float* __restrict__ a2d, const float* __restrict__ tw,
    __nv_bfloat16* __restrict__ hiT, __nv_bfloat16* __restrict__ loT)
{
    __shared__ float t[32][129];
    const int z = blockIdx.y;
    const int b = z >> 2, e = z & 3;
    const int m0 = blockIdx.x * 32;
    const float w = 1.0f / (1.0f + expf(-tw[e]));
    const int tid = threadIdx.x;

    #pragma unroll
    for (int i = 0; i < 16; i++) {
        int idx = tid + i * 256;
        int row = idx >> 7;
        int f   = idx & 127;
        t[row][f] = a2d[((size_t)(b * Nn + m0 + row)) * EF + e * Ff + f] * w;
    }
    __syncthreads();

    const int f    = tid >> 1;
    const int half = tid & 1;
    const int ms   = half * 16;
    __nv_bfloat16 ho[16], lo[16];
    #pragma unroll
    for (int j = 0; j < 16; j++) {
        float v = t[ms + j][f];
        __nv_bfloat16 h = __float2bfloat16(v);
        ho[j] = h;
        lo[j] = __float2bfloat16(v - __bfloat162float(h));
    }
    size_t base = (size_t)z * (Ff * Nn) + (size_t)f * Nn + m0 + ms;
    *(uint4*)&hiT[base]     = *(uint4*)&ho[0];
    *(uint4*)&hiT[base + 8] = *(uint4*)&ho[8];
    *(uint4*)&loT[base]     = *(uint4*)&lo[0];
    *(uint4*)&loT[base + 8] = *(uint4*)&lo[8];
}

// ---------------- mma helpers ------------------------------------------------
__device__ __forceinline__ void ldsm_x4(uint32_t* r, uint32_t addr) {
    asm volatile("ldmatrix.sync.aligned.m8n8.x4.shared.b16 {%0,%1,%2,%3}, [%4];"
        : "=r"(r[0]), "=r"(r[1]), "=r"(r[2]), "=r"(r[3]) : "r"(addr));
}
__device__ __forceinline__ void ldsm_x2(uint32_t* r, uint32_t addr) {
    asm volatile("ldmatrix.sync.aligned.m8n8.x2.shared.b16 {%0,%1}, [%2];"
        : "=r"(r[0]), "=r"(r[1]) : "r"(addr));
}
__device__ __forceinline__ void mma_bf16(float* c, const uint32_t* a, const uint32_t* b) {
    asm volatile(
        "mma.sync.aligned.m16n8k16.row.col.f32.bf16.bf16.f32 "
        "{%0,%1,%2,%3}, {%4,%5,%6,%7}, {%8,%9}, {%0,%1,%2,%3};"
        : "+f"(c[0]), "+f"(c[1]), "+f"(c[2]), "+f"(c[3])
        : "r"(a[0]), "r"(a[1]), "r"(a[2]), "r"(a[3]), "r"(b[0]), "r"(b[1]));
}

// ---------------- flows v2: 512 threads, 256-row M-tile, single wave --------
// Per CTA (z, bm): X[256 n x 128 f] = sum_m mask[z][bm+n][m] * (hi+lo)T[z][f][m]
// grid (4, 32) = 128 CTAs (single wave on 148 SMs), 2-stage cp.async.
// Stage layout (bytes): A 256x(72*2)=36864 | H 128x(72*2)=18432 | L 18432
#define FLW_STRIDE 72
#define FLW_ROWB   (FLW_STRIDE * 2)            // 144 bytes per row
#define FLW_ATILE  (256 * FLW_ROWB)            // 36864
#define FLW_BTILE  (128 * FLW_ROWB)            // 18432
#define FLW_HOFF   FLW_ATILE                   // 36864
#define FLW_LOFF   (FLW_ATILE + FLW_BTILE)     // 55296
#define FLW_STAGE  (FLW_ATILE + 2 * FLW_BTILE) // 73728
#define FLW_SMEM   (2 * FLW_STAGE)             // 147456

__global__ void __launch_bounds__(512, 1) flows_hmma_kernel(
    const __nv_bfloat16* __restrict__ mask,
    const __nv_bfloat16* __restrict__ hiT,
    const __nv_bfloat16* __restrict__ loT,
    float* __restrict__ Xm)
{
    extern __shared__ char smem[];
    const uint32_t su = smem_to_u32(smem);

    const int tid  = threadIdx.x;
    const int wid  = tid >> 5, lane = tid & 31;
    const int wm   = wid & 3;          // 0..3 -> 64-row groups (256 rows total)
    const int wn   = wid >> 2;         // 0..3 -> 32-col f groups (128 cols)
    const int z    = blockIdx.y;
    const int bm   = blockIdx.x * 256;

    const __nv_bfloat16* Asrc = mask + ((size_t)z << 20) + ((size_t)bm << 10);
    const __nv_bfloat16* Hsrc = hiT + (size_t)z * (Ff * Nn);
    const __nv_bfloat16* Lsrc = loT + (size_t)z * (Ff * Nn);

    float acc[4][4][4];
    #pragma unroll
    for (int i = 0; i < 4; i++)
        #pragma unroll
        for (int j = 0; j < 4; j++)
            #pragma unroll
            for (int k = 0; k < 4; k++) acc[i][j][k] = 0.0f;

    const int a_row_l = (lane & 7) + ((lane >> 3) & 1) * 8;
    const int a_kbyte = ((lane >> 4) & 1) * 16;
    const int bl_     = lane & 15;
    const int b_row_l = bl_ & 7;
    const int b_kbyte = (bl_ >> 3) * 16;

    // per-chunk load issue helper geometry: 16B granules
    // A: 256 rows x 8 granules = 2048; B(h,l): 128 x 8 = 1024 each
    // ---- prologue: chunk 0 into stage 0
    {
        const int k0 = 0;
        const uint32_t sb = su;
        #pragma unroll
        for (int i = 0; i < 4; i++) {
            int idx = tid + i * 512;            // 0..2047
            int row = idx >> 3;
            int cg  = (idx & 7) * 8;
            cp_async16(sb + (uint32_t)(row * FLW_ROWB + cg * 2),
                       Asrc + (size_t)row * Nn + k0 + cg);
        }
        #pragma unroll
        for (int i = 0; i < 2; i++) {
            int idx = tid + i * 512;            // 0..1023
            int row = idx >> 3;
            int cg  = (idx & 7) * 8;
            uint32_t so = (uint32_t)(row * FLW_ROWB + cg * 2);
            cp_async16(sb + FLW_HOFF + so, Hsrc + (size_t)row * Nn + k0 + cg);
            cp_async16(sb + FLW_LOFF + so, Lsrc + (size_t)row * Nn + k0 + cg);
        }
        cp_commit();
    }

    for (int c = 0; c < 16; c++) {
        if (c < 15) {
            const int k0 = (c + 1) * 64;
            const uint32_t sb = su + ((c + 1) & 1) * FLW_STAGE;
            #pragma unroll
            for (int i = 0; i < 4; i++) {
                int idx = tid + i * 512;
                int row = idx >> 3;
                int cg  = (idx & 7) * 8;
                cp_async16(sb + (uint32_t)(row * FLW_ROWB + cg * 2),
                           Asrc + (size_t)row * Nn + k0 + cg);
            }
            #pragma unroll
            for (int i = 0; i < 2; i++) {
                int idx = tid + i * 512;
                int row = idx >> 3;
                int cg  = (idx & 7) * 8;
                uint32_t so = (uint32_t)(row * FLW_ROWB + cg * 2);
                cp_async16(sb + FLW_HOFF + so, Hsrc + (size_t)row * Nn + k0 + cg);
                cp_async16(sb + FLW_LOFF + so, Lsrc + (size_t)row * Nn + k0 + cg);
            }
            cp_commit();
            cp_wait<1>();          // chunk c's group complete
        } else {
            cp_wait<0>();
        }
        __syncthreads();

        const uint32_t stg = su + (c & 1) * FLW_STAGE;
        #pragma unroll
        for (int ks = 0; ks < 4; ks++) {
            uint32_t af[4][4];
            #pragma unroll
            for (int mf = 0; mf < 4; mf++) {
                uint32_t addr = stg
                    + (uint32_t)((wm * 64 + mf * 16 + a_row_l) * FLW_ROWB)
                    + (uint32_t)(ks * 32 + a_kbyte);
                ldsm_x4(af[mf], addr);
            }
            uint32_t bh[4][2], bl[4][2];
            #pragma unroll
            for (int nf = 0; nf < 4; nf++) {
                uint32_t rowb = (uint32_t)(wn * 32 + nf * 8 + b_row_l);
                uint32_t addr = stg + FLW_HOFF
                    + rowb * FLW_ROWB + (uint32_t)(ks * 32 + b_kbyte);
                ldsm_x2(bh[nf], addr);
                ldsm_x2(bl[nf], addr + FLW_BTILE);
            }
            #pragma unroll
            for (int mf = 0; mf < 4; mf++)
                #pragma unroll
                for (int nf = 0; nf < 4; nf++) {
                    mma_bf16(acc[mf][nf], af[mf], bh[nf]);
                    mma_bf16(acc[mf][nf], af[mf], bl[nf]);
                }
        }
        __syncthreads();           // all warps done with stage before reuse
    }

    // Epilogue: fp32 X writes
    const int b = z >> 2, e = z & 3;
    const int qr = lane >> 2;              // 0..7
    const int qc = (lane & 3) * 2;         // 0,2,4,6
    #pragma unroll
    for (int mf = 0; mf < 4; mf++) {
        #pragma unroll
        for (int nf = 0; nf < 4; nf++) {
            int n0 = bm + wm * 64 + mf * 16 + qr;
            int f0 = wn * 32 + nf * 8 + qc;
            float2 v0 = { acc[mf][nf][0], acc[mf][nf][1] };
            float2 v1 = { acc[mf][nf][2], acc[mf][nf][3] };
            *(float2*)(Xm + ((size_t)(b * Nn + n0)) * EF + e * Ff + f0)     = v0;
            *(float2*)(Xm + ((size_t)(b * Nn + n0 + 8)) * EF + e * Ff + f0) = v1;
        }
    }
}

// ---------------- generic NT SGEMM with register prefetch -------------------
// C = A(MxK) * B(NxK)^T + bias. 128x128x16 tile, 256 threads, 8x8 microtile.
__global__ void __launch_bounds__(256, 2) sgemm_nt_kernel(
    const float* __restrict__ A, int lda,
    const float* __restrict__ B,
    const float* __restrict__ bias,
    float* __restrict__ C, int ldc,
    int K)
{
    __shared__ float As[16][128];
    __shared__ float Bs[16][128];

    const int bm = blockIdx.x * 128;
    const int bn = blockIdx.y * 128;
    const int tid = threadIdx.x;

    const int l_row = tid >> 2;          // 0..63
    const int l_col = (tid & 3) * 4;     // 0,4,8,12
    const int ty = tid >> 4;             // 0..15
    const int tx = tid & 15;             // 0..15

    float acc[8][8];
    #pragma unroll
    for (int i = 0; i < 8; i++)
        #pragma unroll
        for (int j = 0; j < 8; j++) acc[i][j] = 0.0f;

    // prologue fetch (chunk 0) into registers
    float4 av0 = *(const float4*)&A[(size_t)(bm + l_row) * lda + l_col];
    float4 av1 = *(const float4*)&A[(size_t)(bm + l_row + 64) * lda + l_col];
    float4 bv0 = *(const float4*)&B[(size_t)(bn + l_row) * K + l_col];
    float4 bv1 = *(const float4*)&B[(size_t)(bn + l_row + 64) * K + l_col];

    for (int k0 = 0; k0 < K; k0 += 16) {
        As[l_col + 0][l_row] = av0.x; As[l_col + 1][l_row] = av0.y;
        As[l_col + 2][l_row] = av0.z; As[l_col + 3][l_row] = av0.w;
        As[l_col + 0][l_row + 64] = av1.x; As[l_col + 1][l_row + 64] = av1.y;
        As[l_col + 2][l_row + 64] = av1.z; As[l_col + 3][l_row + 64] = av1.w;
        Bs[l_col + 0][l_row] = bv0.x; Bs[l_col + 1][l_row] = bv0.y;
        Bs[l_col + 2][l_row] = bv0.z; Bs[l_col + 3][l_row] = bv0.w;
        Bs[l_col + 0][l_row + 64] = bv1.x; Bs[l_col + 1][l_row + 64] = bv1.y;
        Bs[l_col + 2][l_row + 64] = bv1.z; Bs[l_col + 3][l_row + 64] = bv1.w;
        __syncthreads();

        if (k0 + 16 < K) {
            av0 = *(const float4*)&A[(size_t)(bm + l_row) * lda + k0 + 16 + l_col];
            av1 = *(const float4*)&A[(size_t)(bm + l_row + 64) * lda + k0 + 16 + l_col];
            bv0 = *(const float4*)&B[(size_t)(bn + l_row) * K + k0 + 16 + l_col];
            bv1 = *(const float4*)&B[(size_t)(bn + l_row + 64) * K + k0 + 16 + l_col];
        }

        #pragma unroll
        for (int k = 0; k < 16; k++) {
            float ar[8], br[8];
            #pragma unroll
            for (int i = 0; i < 8; i++) ar[i] = As[k][ty * 8 + i];
            #pragma unroll
            for (int j = 0; j < 8; j++) br[j] = Bs[k][tx * 8 + j];
            #pragma unroll
            for (int i = 0; i < 8; i++)
                #pragma unroll
                for (int j = 0; j < 8; j++) acc[i][j] += ar[i] * br[j];
        }
        __syncthreads();
    }

    #pragma unroll
    for (int i = 0; i < 8; i++) {
        size_t r = (size_t)(bm + ty * 8 + i);
        #pragma unroll
        for (int j = 0; j < 8; j += 4) {
            int c = tx * 8 + j;
            float4 v;
            v.x = acc[i][j + 0] + bias[bn + c + 0];
            v.y = acc[i][j + 1] + bias[bn + c + 1];
            v.z = acc[i][j + 2] + bias[bn + c + 2];
            v.w = acc[i][j + 3] + bias[bn + c + 3];
            *(float4*)&C[r * ldc + bn + c] = v;
        }
    }
}

// ---------------- fused GRU cell elementwise --------------------------------
__global__ void __launch_bounds__(256) gru_kernel(
    const float* __restrict__ gi,
    const float* __restrict__ gh,
    const float* __restrict__ h,
    float* __restrict__ out_final,
    int last)
{
    size_t idx = (size_t)blockIdx.x * blockDim.x + threadIdx.x;
    int i = (int)(idx >> 7), f = (int)(idx & 127);
    const float* gir = gi + (size_t)i * G3F;
    const float* ghr = gh + (size_t)i * G3F;
    float i_r = gir[f], i_z = gir[128 + f], i_n = gir[256 + f];
    float h_r = ghr[f], h_z = ghr[128 + f], h_n = ghr[256 + f];
    float hv  = h[idx];
    float r = 1.0f / (1.0f + expf(-(i_r + h_r)));
    float z = 1.0f / (1.0f + expf(-(i_z + h_z)));
    float n = tanhf(i_n + r * h_n);
    float nh = (1.0f - z) * n + z * hv;
    if (last) out_final[idx] = nh;
    else      h_buf[idx] = nh;
}

// ---------------- launch ----------------------------------------------------
extern "C" void kernel_launch(void* const* d_in, const int* in_sizes, int n_in,
                              void* d_out, int out_size)
{
    const float* feats  = (const float*)d_in[0];
    const int*   graphs = (const int*)d_in[1];         // int32 (JAX default)
    const float* fc_w   = (const float*)d_in[2];       // (512,128)
    const float* fc_b   = (const float*)d_in[3];       // (512,)
    const float* tw     = (const float*)d_in[4];
    const float* w_ih   = (const float*)d_in[5];       // (384,512)
    const float* w_hh   = (const float*)d_in[6];       // (384,128)
    const float* b_ih   = (const float*)d_in[7];
    const float* b_hh   = (const float*)d_in[8];
    float*       out    = (float*)d_out;

    __nv_bfloat16 *mask_p, *hiT_p, *loT_p;
    float *a_p, *x_p, *gi_p, *gh_p, *h_p;
    cudaGetSymbolAddress((void**)&mask_p, mask_bf);
    cudaGetSymbolAddress((void**)&hiT_p,  ahiT_buf);
    cudaGetSymbolAddress((void**)&loT_p,  aloT_buf);
    cudaGetSymbolAddress((void**)&a_p,  a_buf);
    cudaGetSymbolAddress((void**)&x_p,  x_buf);
    cudaGetSymbolAddress((void**)&gi_p, gi_buf);
    cudaGetSymbolAddress((void**)&gh_p, gh_buf);
    cudaGetSymbolAddress((void**)&h_p,  h_buf);

    cudaFuncSetAttribute(flows_hmma_kernel,
                         cudaFuncAttributeMaxDynamicSharedMemorySize, FLW_SMEM);

    // One-time per launch
    {
        size_t total = (size_t)Bsz * Ee * Nn * Nn;   // 33,554,432
        convert_mask_kernel<<<(unsigned)(total / (256 * 4)), 256>>>(graphs, mask_p);
        copy_h_kernel<<<(MROWS * Ff) / 256, 256>>>(feats, h_p);
    }

    for (int s = 0; s < NSTEPS; s++) {
        // a2d = h @ fc_w^T + fc_b   (8192 x 512, K=128)
        {
            dim3 grid(MROWS / 128, EF / 128);
            sgemm_nt_kernel<<<grid, 256>>>(h_p, Ff, fc_w, fc_b, a_p, EF, Ff);
        }
        // a' = w_e*a2d, hi/lo split + transpose -> [z][f][m]
        {
            dim3 grid(Nn / 32, Bsz * Ee);
            convert_a_kernel<<<grid, 256>>>(a_p, tw, hiT_p, loT_p);
        }
        // flows = mask @ a'  via mma.sync bf16, 256-row tiles, single wave
        {
            dim3 grid(Nn / 256, Bsz * Ee);
            flows_hmma_kernel<<<grid, 512, FLW_SMEM>>>(mask_p, hiT_p, loT_p, x_p);
        }
        // gi = x @ w_ih^T + b_ih   (8192 x 384, K=512)
        {
            dim3 grid(MROWS / 128, G3F / 128);
            sgemm_nt_kernel<<<grid, 256>>>(x_p, EF, w_ih, b_ih, gi_p, G3F, EF);
        }
        // gh = h @ w_hh^T + b_hh   (8192 x 384, K=128)
        {
            dim3 grid(MROWS / 128, G3F / 128);
            sgemm_nt_kernel<<<grid, 256>>>(h_p, Ff, w_hh, b_hh, gh_p, G3F, Ff);
        }
        // GRU cell
        gru_kernel<<<(MROWS * Ff) / 256, 256>>>(gi_p, gh_p, h_p, out,
                                                (s == NSTEPS - 1) ? 1 : 0);
    }
}

// round 11
// speedup vs baseline: 1.6729x; 1.0027x over previous
#include <cuda_runtime.h>
#include <cuda_bf16.h>
#include <math.h>
#include <cstdint>

// Problem constants (fixed by the dataset)
#define Bsz 8
#define Nn  1024
#define Ff  128
#define Ee  4
#define NSTEPS 5

#define MROWS (Bsz * Nn)       // 8192
#define EF    (Ee * Ff)        // 512
#define G3F   (3 * Ff)         // 384

// ---------------- scratch (device globals: no allocations allowed) ----------
__device__ __nv_bfloat16 mask_bf [(size_t)Bsz * Ee * Nn * Nn];  // 64MB, {0,1}
__device__ __nv_bfloat16 ahiT_buf[(size_t)Bsz * Ee * Ff * Nn];  // [z][f][m] 8MB
__device__ __nv_bfloat16 aloT_buf[(size_t)Bsz * Ee * Ff * Nn];  // [z][f][m] 8MB
__device__ float a_buf [(size_t)MROWS * EF];
__device__ float x_buf [(size_t)MROWS * EF];
__device__ float gi_buf[(size_t)MROWS * G3F];
__device__ float gh_buf[(size_t)MROWS * G3F];
__device__ float h_buf [(size_t)MROWS * Ff];

__device__ __forceinline__ uint32_t smem_to_u32(const void* smem_ptr) {
    uint32_t addr;
    asm("{ .reg .u64 tmp; cvta.to.shared.u64 tmp, %1; cvt.u32.u64 %0, tmp; }"
        : "=r"(addr) : "l"(smem_ptr));
    return addr;
}

// ---------------- cp.async helpers (sm_80+ baseline ISA) --------------------
__device__ __forceinline__ void cp_async16(uint32_t smem_addr, const void* gptr) {
    asm volatile("cp.async.cg.shared.global [%0], [%1], 16;"
        :: "r"(smem_addr), "l"(gptr));
}
__device__ __forceinline__ void cp_commit() {
    asm volatile("cp.async.commit_group;" ::: "memory");
}
template<int N> __device__ __forceinline__ void cp_wait() {
    asm volatile("cp.async.wait_group %0;" :: "n"(N) : "memory");
}

// ---------------- one-time: mask -> bf16 {0,1} ------------------------------
__global__ void __launch_bounds__(256) convert_mask_kernel(
    const int* __restrict__ graphs, __nv_bfloat16* __restrict__ mask)
{
    size_t idx4 = ((size_t)blockIdx.x * blockDim.x + threadIdx.x) * 4;
    int4 gv = *(const int4*)&graphs[idx4];
    __nv_bfloat16 o[4];
    o[0] = __float2bfloat16((float)gv.x);
    o[1] = __float2bfloat16((float)gv.y);
    o[2] = __float2bfloat16((float)gv.z);
    o[3] = __float2bfloat16((float)gv.w);
    *(uint2*)&mask[idx4] = *(uint2*)o;
}

__global__ void __launch_bounds__(256) copy_h_kernel(
    const float* __restrict__ src, float* __restrict__ dst)
{
    size_t idx = (size_t)blockIdx.x * blockDim.x + threadIdx.x;
    dst[idx] = src[idx];
}

// ---------------- per-step: a' = w_e * a2d, split hi/lo, transpose ----------
__global__ void __launch_bounds__(256) convert_a_kernel(
    const float* __restrict__ a2d, const float* __restrict__ tw,
    __nv_bfloat16* __restrict__ hiT, __nv_bfloat16* __restrict__ loT)
{
    __shared__ float t[32][129];
    const int z = blockIdx.y;
    const int b = z >> 2, e = z & 3;
    const int m0 = blockIdx.x * 32;
    const float w = 1.0f / (1.0f + expf(-tw[e]));
    const int tid = threadIdx.x;

    #pragma unroll
    for (int i = 0; i < 16; i++) {
        int idx = tid + i * 256;
        int row = idx >> 7;
        int f   = idx & 127;
        t[row][f] = a2d[((size_t)(b * Nn + m0 + row)) * EF + e * Ff + f] * w;
    }
    __syncthreads();

    const int f    = tid >> 1;
    const int half = tid & 1;
    const int ms   = half * 16;
    __nv_bfloat16 ho[16], lo[16];
    #pragma unroll
    for (int j = 0; j < 16; j++) {
        float v = t[ms + j][f];
        __nv_bfloat16 h = __float2bfloat16(v);
        ho[j] = h;
        lo[j] = __float2bfloat16(v - __bfloat162float(h));
    }
    size_t base = (size_t)z * (Ff * Nn) + (size_t)f * Nn + m0 + ms;
    *(uint4*)&hiT[base]     = *(uint4*)&ho[0];
    *(uint4*)&hiT[base + 8] = *(uint4*)&ho[8];
    *(uint4*)&loT[base]     = *(uint4*)&lo[0];
    *(uint4*)&loT[base + 8] = *(uint4*)&lo[8];
}

// ---------------- mma helpers ------------------------------------------------
__device__ __forceinline__ void ldsm_x4(uint32_t* r, uint32_t addr) {
    asm volatile("ldmatrix.sync.aligned.m8n8.x4.shared.b16 {%0,%1,%2,%3}, [%4];"
        : "=r"(r[0]), "=r"(r[1]), "=r"(r[2]), "=r"(r[3]) : "r"(addr));
}
__device__ __forceinline__ void ldsm_x2(uint32_t* r, uint32_t addr) {
    asm volatile("ldmatrix.sync.aligned.m8n8.x2.shared.b16 {%0,%1}, [%2];"
        : "=r"(r[0]), "=r"(r[1]) : "r"(addr));
}
__device__ __forceinline__ void mma_bf16(float* c, const uint32_t* a, const uint32_t* b) {
    asm volatile(
        "mma.sync.aligned.m16n8k16.row.col.f32.bf16.bf16.f32 "
        "{%0,%1,%2,%3}, {%4,%5,%6,%7}, {%8,%9}, {%0,%1,%2,%3};"
        : "+f"(c[0]), "+f"(c[1]), "+f"(c[2]), "+f"(c[3])
        : "r"(a[0]), "r"(a[1]), "r"(a[2]), "r"(a[3]), "r"(b[0]), "r"(b[1]));
}

// ---------------- flows v2: 512 threads, 256-row M-tile, single wave --------
// Per CTA (z, bm): X[256 n x 128 f] = sum_m mask[z][bm+n][m] * (hi+lo)T[z][f][m]
// grid (4, 32) = 128 CTAs (single wave on 148 SMs), 2-stage cp.async.
// Stage layout (bytes): A 256x(72*2)=36864 | H 128x(72*2)=18432 | L 18432
#define FLW_STRIDE 72
#define FLW_ROWB   (FLW_STRIDE * 2)            // 144 bytes per row
#define FLW_ATILE  (256 * FLW_ROWB)            // 36864
#define FLW_BTILE  (128 * FLW_ROWB)            // 18432
#define FLW_HOFF   FLW_ATILE                   // 36864
#define FLW_LOFF   (FLW_ATILE + FLW_BTILE)     // 55296
#define FLW_STAGE  (FLW_ATILE + 2 * FLW_BTILE) // 73728
#define FLW_SMEM   (2 * FLW_STAGE)             // 147456

__global__ void __launch_bounds__(512, 1) flows_hmma_kernel(
    const __nv_bfloat16* __restrict__ mask,
    const __nv_bfloat16* __restrict__ hiT,
    const __nv_bfloat16* __restrict__ loT,
    float* __restrict__ Xm)
{
    extern __shared__ char smem[];
    const uint32_t su = smem_to_u32(smem);

    const int tid  = threadIdx.x;
    const int wid  = tid >> 5, lane = tid & 31;
    const int wm   = wid & 3;          // 0..3 -> 64-row groups (256 rows total)
    const int wn   = wid >> 2;         // 0..3 -> 32-col f groups (128 cols)
    const int z    = blockIdx.y;
    const int bm   = blockIdx.x * 256;

    const __nv_bfloat16* Asrc = mask + ((size_t)z << 20) + ((size_t)bm << 10);
    const __nv_bfloat16* Hsrc = hiT + (size_t)z * (Ff * Nn);
    const __nv_bfloat16* Lsrc = loT + (size_t)z * (Ff * Nn);

    float acc[4][4][4];
    #pragma unroll
    for (int i = 0; i < 4; i++)
        #pragma unroll
        for (int j = 0; j < 4; j++)
            #pragma unroll
            for (int k = 0; k < 4; k++) acc[i][j][k] = 0.0f;

    const int a_row_l = (lane & 7) + ((lane >> 3) & 1) * 8;
    const int a_kbyte = ((lane >> 4) & 1) * 16;
    const int bl_     = lane & 15;
    const int b_row_l = bl_ & 7;
    const int b_kbyte = (bl_ >> 3) * 16;

    // per-chunk load issue helper geometry: 16B granules
    // A: 256 rows x 8 granules = 2048; B(h,l): 128 x 8 = 1024 each
    // ---- prologue: chunk 0 into stage 0
    {
        const int k0 = 0;
        const uint32_t sb = su;
        #pragma unroll
        for (int i = 0; i < 4; i++) {
            int idx = tid + i * 512;            // 0..2047
            int row = idx >> 3;
            int cg  = (idx & 7) * 8;
            cp_async16(sb + (uint32_t)(row * FLW_ROWB + cg * 2),
                       Asrc + (size_t)row * Nn + k0 + cg);
        }
        #pragma unroll
        for (int i = 0; i < 2; i++) {
            int idx = tid + i * 512;            // 0..1023
            int row = idx >> 3;
            int cg  = (idx & 7) * 8;
            uint32_t so = (uint32_t)(row * FLW_ROWB + cg * 2);
            cp_async16(sb + FLW_HOFF + so, Hsrc + (size_t)row * Nn + k0 + cg);
            cp_async16(sb + FLW_LOFF + so, Lsrc + (size_t)row * Nn + k0 + cg);
        }
        cp_commit();
    }

    for (int c = 0; c < 16; c++) {
        if (c < 15) {
            const int k0 = (c + 1) * 64;
            const uint32_t sb = su + ((c + 1) & 1) * FLW_STAGE;
            #pragma unroll
            for (int i = 0; i < 4; i++) {
                int idx = tid + i * 512;
                int row = idx >> 3;
                int cg  = (idx & 7) * 8;
                cp_async16(sb + (uint32_t)(row * FLW_ROWB + cg * 2),
                           Asrc + (size_t)row * Nn + k0 + cg);
            }
            #pragma unroll
            for (int i = 0; i < 2; i++) {
                int idx = tid + i * 512;
                int row = idx >> 3;
                int cg  = (idx & 7) * 8;
                uint32_t so = (uint32_t)(row * FLW_ROWB + cg * 2);
                cp_async16(sb + FLW_HOFF + so, Hsrc + (size_t)row * Nn + k0 + cg);
                cp_async16(sb + FLW_LOFF + so, Lsrc + (size_t)row * Nn + k0 + cg);
            }
            cp_commit();
            cp_wait<1>();          // chunk c's group complete
        } else {
            cp_wait<0>();
        }
        __syncthreads();

        const uint32_t stg = su + (c & 1) * FLW_STAGE;
        #pragma unroll
        for (int ks = 0; ks < 4; ks++) {
            uint32_t af[4][4];
            #pragma unroll
            for (int mf = 0; mf < 4; mf++) {
                uint32_t addr = stg
                    + (uint32_t)((wm * 64 + mf * 16 + a_row_l) * FLW_ROWB)
                    + (uint32_t)(ks * 32 + a_kbyte);
                ldsm_x4(af[mf], addr);
            }
            uint32_t bh[4][2], bl[4][2];
            #pragma unroll
            for (int nf = 0; nf < 4; nf++) {
                uint32_t rowb = (uint32_t)(wn * 32 + nf * 8 + b_row_l);
                uint32_t addr = stg + FLW_HOFF
                    + rowb * FLW_ROWB + (uint32_t)(ks * 32 + b_kbyte);
                ldsm_x2(bh[nf], addr);
                ldsm_x2(bl[nf], addr + FLW_BTILE);
            }
            #pragma unroll
            for (int mf = 0; mf < 4; mf++)
                #pragma unroll
                for (int nf = 0; nf < 4; nf++) {
                    mma_bf16(acc[mf][nf], af[mf], bh[nf]);
                    mma_bf16(acc[mf][nf], af[mf], bl[nf]);
                }
        }
        __syncthreads();           // all warps done with stage before reuse
    }

    // Epilogue: fp32 X writes
    const int b = z >> 2, e = z & 3;
    const int qr = lane >> 2;              // 0..7
    const int qc = (lane & 3) * 2;         // 0,2,4,6
    #pragma unroll
    for (int mf = 0; mf < 4; mf++) {
        #pragma unroll
        for (int nf = 0; nf < 4; nf++) {
            int n0 = bm + wm * 64 + mf * 16 + qr;
            int f0 = wn * 32 + nf * 8 + qc;
            float2 v0 = { acc[mf][nf][0], acc[mf][nf][1] };
            float2 v1 = { acc[mf][nf][2], acc[mf][nf][3] };
            *(float2*)(Xm + ((size_t)(b * Nn + n0)) * EF + e * Ff + f0)     = v0;
            *(float2*)(Xm + ((size_t)(b * Nn + n0 + 8)) * EF + e * Ff + f0) = v1;
        }
    }
}

// ---------------- generic NT SGEMM with register prefetch -------------------
// C = A(MxK) * B(NxK)^T + bias. 128x128x16 tile, 256 threads, 8x8 microtile.
__global__ void __launch_bounds__(256, 2) sgemm_nt_kernel(
    const float* __restrict__ A, int lda,
    const float* __restrict__ B,
    const float* __restrict__ bias,
    float* __restrict__ C, int ldc,
    int K)
{
    __shared__ float As[16][128];
    __shared__ float Bs[16][128];

    const int bm = blockIdx.x * 128;
    const int bn = blockIdx.y * 128;
    const int tid = threadIdx.x;

    const int l_row = tid >> 2;          // 0..63
    const int l_col = (tid & 3) * 4;     // 0,4,8,12
    const int ty = tid >> 4;             // 0..15
    const int tx = tid & 15;             // 0..15

    float acc[8][8];
    #pragma unroll
    for (int i = 0; i < 8; i++)
        #pragma unroll
        for (int j = 0; j < 8; j++) acc[i][j] = 0.0f;

    // prologue fetch (chunk 0) into registers
    float4 av0 = *(const float4*)&A[(size_t)(bm + l_row) * lda + l_col];
    float4 av1 = *(const float4*)&A[(size_t)(bm + l_row + 64) * lda + l_col];
    float4 bv0 = *(const float4*)&B[(size_t)(bn + l_row) * K + l_col];
    float4 bv1 = *(const float4*)&B[(size_t)(bn + l_row + 64) * K + l_col];

    for (int k0 = 0; k0 < K; k0 += 16) {
        As[l_col + 0][l_row] = av0.x; As[l_col + 1][l_row] = av0.y;
        As[l_col + 2][l_row] = av0.z; As[l_col + 3][l_row] = av0.w;
        As[l_col + 0][l_row + 64] = av1.x; As[l_col + 1][l_row + 64] = av1.y;
        As[l_col + 2][l_row + 64] = av1.z; As[l_col + 3][l_row + 64] = av1.w;
        Bs[l_col + 0][l_row] = bv0.x; Bs[l_col + 1][l_row] = bv0.y;
        Bs[l_col + 2][l_row] = bv0.z; Bs[l_col + 3][l_row] = bv0.w;
        Bs[l_col + 0][l_row + 64] = bv1.x; Bs[l_col + 1][l_row + 64] = bv1.y;
        Bs[l_col + 2][l_row + 64] = bv1.z; Bs[l_col + 3][l_row + 64] = bv1.w;
        __syncthreads();

        if (k0 + 16 < K) {
            av0 = *(const float4*)&A[(size_t)(bm + l_row) * lda + k0 + 16 + l_col];
            av1 = *(const float4*)&A[(size_t)(bm + l_row + 64) * lda + k0 + 16 + l_col];
            bv0 = *(const float4*)&B[(size_t)(bn + l_row) * K + k0 + 16 + l_col];
            bv1 = *(const float4*)&B[(size_t)(bn + l_row + 64) * K + k0 + 16 + l_col];
        }

        #pragma unroll
        for (int k = 0; k < 16; k++) {
            float ar[8], br[8];
            #pragma unroll
            for (int i = 0; i < 8; i++) ar[i] = As[k][ty * 8 + i];
            #pragma unroll
            for (int j = 0; j < 8; j++) br[j] = Bs[k][tx * 8 + j];
            #pragma unroll
            for (int i = 0; i < 8; i++)
                #pragma unroll
                for (int j = 0; j < 8; j++) acc[i][j] += ar[i] * br[j];
        }
        __syncthreads();
    }

    #pragma unroll
    for (int i = 0; i < 8; i++) {
        size_t r = (size_t)(bm + ty * 8 + i);
        #pragma unroll
        for (int j = 0; j < 8; j += 4) {
            int c = tx * 8 + j;
            float4 v;
            v.x = acc[i][j + 0] + bias[bn + c + 0];
            v.y = acc[i][j + 1] + bias[bn + c + 1];
            v.z = acc[i][j + 2] + bias[bn + c + 2];
            v.w = acc[i][j + 3] + bias[bn + c + 3];
            *(float4*)&C[r * ldc + bn + c] = v;
        }
    }
}

// ---------------- fused GRU cell elementwise --------------------------------
__global__ void __launch_bounds__(256) gru_kernel(
    const float* __restrict__ gi,
    const float* __restrict__ gh,
    const float* __restrict__ h,
    float* __restrict__ out_final,
    int last)
{
    size_t idx = (size_t)blockIdx.x * blockDim.x + threadIdx.x;
    int i = (int)(idx >> 7), f = (int)(idx & 127);
    const float* gir = gi + (size_t)i * G3F;
    const float* ghr = gh + (size_t)i * G3F;
    float i_r = gir[f], i_z = gir[128 + f], i_n = gir[256 + f];
    float h_r = ghr[f], h_z = ghr[128 + f], h_n = ghr[256 + f];
    float hv  = h[idx];
    float r = 1.0f / (1.0f + expf(-(i_r + h_r)));
    float z = 1.0f / (1.0f + expf(-(i_z + h_z)));
    float n = tanhf(i_n + r * h_n);
    float nh = (1.0f - z) * n + z * hv;
    if (last) out_final[idx] = nh;
    else      h_buf[idx] = nh;
}

// ---------------- launch ----------------------------------------------------
extern "C" void kernel_launch(void* const* d_in, const int* in_sizes, int n_in,
                              void* d_out, int out_size)
{
    const float* feats  = (const float*)d_in[0];
    const int*   graphs = (const int*)d_in[1];         // int32 (JAX default)
    const float* fc_w   = (const float*)d_in[2];       // (512,128)
    const float* fc_b   = (const float*)d_in[3];       // (512,)
    const float* tw     = (const float*)d_in[4];
    const float* w_ih   = (const float*)d_in[5];       // (384,512)
    const float* w_hh   = (const float*)d_in[6];       // (384,128)
    const float* b_ih   = (const float*)d_in[7];
    const float* b_hh   = (const float*)d_in[8];
    float*       out    = (float*)d_out;

    __nv_bfloat16 *mask_p, *hiT_p, *loT_p;
    float *a_p, *x_p, *gi_p, *gh_p, *h_p;
    cudaGetSymbolAddress((void**)&mask_p, mask_bf);
    cudaGetSymbolAddress((void**)&hiT_p,  ahiT_buf);
    cudaGetSymbolAddress((void**)&loT_p,  aloT_buf);
    cudaGetSymbolAddress((void**)&a_p,  a_buf);
    cudaGetSymbolAddress((void**)&x_p,  x_buf);
    cudaGetSymbolAddress((void**)&gi_p, gi_buf);
    cudaGetSymbolAddress((void**)&gh_p, gh_buf);
    cudaGetSymbolAddress((void**)&h_p,  h_buf);

    cudaFuncSetAttribute(flows_hmma_kernel,
                         cudaFuncAttributeMaxDynamicSharedMemorySize, FLW_SMEM);

    // One-time per launch
    {
        size_t total = (size_t)Bsz * Ee * Nn * Nn;   // 33,554,432
        convert_mask_kernel<<<(unsigned)(total / (256 * 4)), 256>>>(graphs, mask_p);
        copy_h_kernel<<<(MROWS * Ff) / 256, 256>>>(feats, h_p);
    }

    for (int s = 0; s < NSTEPS; s++) {
        // a2d = h @ fc_w^T + fc_b   (8192 x 512, K=128)
        {
            dim3 grid(MROWS / 128, EF / 128);
            sgemm_nt_kernel<<<grid, 256>>>(h_p, Ff, fc_w, fc_b, a_p, EF, Ff);
        }
        // a' = w_e*a2d, hi/lo split + transpose -> [z][f][m]
        {
            dim3 grid(Nn / 32, Bsz * Ee);
            convert_a_kernel<<<grid, 256>>>(a_p, tw, hiT_p, loT_p);
        }
        // flows = mask @ a'  via mma.sync bf16, 256-row tiles, single wave
        {
            dim3 grid(Nn / 256, Bsz * Ee);
            flows_hmma_kernel<<<grid, 512, FLW_SMEM>>>(mask_p, hiT_p, loT_p, x_p);
        }
        // gi = x @ w_ih^T + b_ih   (8192 x 384, K=512)
        {
            dim3 grid(MROWS / 128, G3F / 128);
            sgemm_nt_kernel<<<grid, 256>>>(x_p, EF, w_ih, b_ih, gi_p, G3F, EF);
        }
        // gh = h @ w_hh^T + b_hh   (8192 x 384, K=128)
        {
            dim3 grid(MROWS / 128, G3F / 128);
            sgemm_nt_kernel<<<grid, 256>>>(h_p, Ff, w_hh, b_hh, gh_p, G3F, Ff);
        }
        // GRU cell
        gru_kernel<<<(MROWS * Ff) / 256, 256>>>(gi_p, gh_p, h_p, out,
                                                (s == NSTEPS - 1) ? 1 : 0);
    }
}